// round 1
// baseline (speedup 1.0000x reference)
#include <cuda_runtime.h>

#define BB   32
#define NN   16384
#define CKD  16
#define NS   14
#define MAXM 8192
#define MAXCH 64

// ---------------- device scratch (static, no allocations) ----------------
__device__ __align__(256) float g_x0 [BB*MAXM*CKD];
__device__ __align__(256) float g_x1 [BB*MAXM*CKD];
__device__ __align__(256) float g_d  [BB*MAXM*CKD];
__device__ __align__(256) float g_Ud [BB*(NN-1)*CKD];
__device__ __align__(256) float g_Us [BB*(NN-1)*CKD];
__device__ __align__(256) float g_part[2ull*BB*MAXCH*64*CKD*2];
__device__ __align__(256) float g_spec[2*BB*64*2*CKD];
__device__ __align__(256) float g_tabc[MAXM*64];
__device__ __align__(256) float g_tabs[MAXM*64];
__device__ __align__(256) float g_tabT[64*MAXM*2];   // (cos,sin) interleaved, f-major
__device__ __align__(256) float g_wT  [6*64*16*16];  // [arr][f][i][o]

// ---------------- twiddle tables ----------------
__global__ void tab_row_kernel() {
    int idx = blockIdx.x * blockDim.x + threadIdx.x;   // t*64 + f
    int t = idx >> 6, f = idx & 63;
    float ph = (float)(f * t) * (2.0f / 8192.0f);      // exact: f*t < 2^24, /2^12 exact
    float s, c; sincospif(ph, &s, &c);
    g_tabc[idx] = c;
    g_tabs[idx] = s;
}
__global__ void tab_T_kernel() {
    int idx = blockIdx.x * blockDim.x + threadIdx.x;   // f*8192 + t
    int f = idx >> 13, t = idx & 8191;
    float ph = (float)(f * t) * (2.0f / 8192.0f);
    float s, c; sincospif(ph, &s, &c);
    g_tabT[2*idx + 0] = c;
    g_tabT[2*idx + 1] = s;
}

// ---------------- weight transpose: [i][o][f] -> [arr][f][i][o] ----------------
__global__ void wprep_kernel(const float* __restrict__ a0, const float* __restrict__ a1,
                             const float* __restrict__ a2, const float* __restrict__ a3,
                             const float* __restrict__ a4, const float* __restrict__ a5) {
    int idx = blockIdx.x * blockDim.x + threadIdx.x;   // 6*64*256
    if (idx >= 6*16384) return;
    int arr = idx >> 14;
    int r   = idx & 16383;
    int f = r >> 8, i = (r >> 4) & 15, o = r & 15;
    const float* src = (arr == 0) ? a0 : (arr == 1) ? a1 : (arr == 2) ? a2 :
                       (arr == 3) ? a3 : (arr == 4) ? a4 : a5;
    g_wT[idx] = src[(i * 16 + o) * 64 + f];
}

// ---------------- wavelet decomposition step ----------------
__global__ void decompose_kernel(const float* __restrict__ xin,
                                 const float* __restrict__ ecd, const float* __restrict__ ecs,
                                 float* __restrict__ dout, float* __restrict__ xout, int half) {
    __shared__ float sd[32], ss[32];
    int tid = threadIdx.x;
    if (tid < 32)      sd[tid]      = ecd[tid];
    else if (tid < 64) ss[tid - 32] = ecs[tid - 32];
    __syncthreads();
    int idx = blockIdx.x * blockDim.x + tid;
    if (idx >= BB * half * 4) return;
    int c = idx & 3;
    int s = (idx >> 2) % half;
    int b = idx / (half * 4);
    size_t rin = (((size_t)b * (2 * half) + 2 * s) * 16) + c * 4;
    float4 A0 = *(const float4*)&xin[rin];
    float4 A1 = *(const float4*)&xin[rin + 16];
    float xa[8] = {A0.x, A0.y, A0.z, A0.w, A1.x, A1.y, A1.z, A1.w};
    float dv[4] = {0, 0, 0, 0}, sv[4] = {0, 0, 0, 0};
#pragma unroll
    for (int p = 0; p < 8; p++) {
#pragma unroll
        for (int j = 0; j < 4; j++) {
            dv[j] += xa[p] * sd[p * 4 + j];
            sv[j] += xa[p] * ss[p * 4 + j];
        }
    }
    size_t rout = (((size_t)b * half + s) * 16) + c * 4;
    *(float4*)&dout[rout] = make_float4(dv[0], dv[1], dv[2], dv[3]);
    *(float4*)&xout[rout] = make_float4(sv[0], sv[1], sv[2], sv[3]);
}

// ---------------- forward truncated DFT (split-K partials, d & x together) ----------------
__global__ void __launch_bounds__(64) fwd_kernel(const float* __restrict__ dA,
                                                 const float* __restrict__ xA,
                                                 int m, int stride, int nchunk) {
    int b = blockIdx.x, ch = blockIdx.y;
    int clen = m / nchunk;
    int t0 = ch * clen;
    int tid = threadIdx.x;
    int i0 = (tid & 3) * 4;
    int f0 = (tid >> 2) * 4;
    const float* dB = dA + (size_t)b * m * 16;
    const float* xB = xA + (size_t)b * m * 16;
    float aDr[4][4] = {}, aDi[4][4] = {}, aXr[4][4] = {}, aXi[4][4] = {};
    __shared__ __align__(16) float s_d[32][16];
    __shared__ __align__(16) float s_x[32][16];
    __shared__ __align__(16) float s_c[32][64];
    __shared__ __align__(16) float s_s[32][64];

    for (int tb = 0; tb < clen; tb += 32) {
        int nt = clen - tb; if (nt > 32) nt = 32;
        for (int idx2 = tid; idx2 < 128; idx2 += 64) {
            int tt = idx2 >> 2, q = (idx2 & 3) * 4;
            float4 v = make_float4(0, 0, 0, 0), w = v;
            if (tt < nt) {
                size_t rr = (size_t)(t0 + tb + tt) * 16 + q;
                v = *(const float4*)&dB[rr];
                w = *(const float4*)&xB[rr];
            }
            *(float4*)&s_d[tt][q] = v;
            *(float4*)&s_x[tt][q] = w;
        }
        for (int idx2 = tid; idx2 < 512; idx2 += 64) {
            int tt = idx2 >> 4, q = (idx2 & 15) * 4;
            int tg = (tt < nt) ? (t0 + tb + tt) * stride : 0;
            *(float4*)&s_c[tt][q] = *(const float4*)&g_tabc[(size_t)tg * 64 + q];
            *(float4*)&s_s[tt][q] = *(const float4*)&g_tabs[(size_t)tg * 64 + q];
        }
        __syncthreads();
#pragma unroll 8
        for (int tt = 0; tt < 32; tt++) {
            float4 dv = *(const float4*)&s_d[tt][i0];
            float4 xv = *(const float4*)&s_x[tt][i0];
            float4 cv = *(const float4*)&s_c[tt][f0];
            float4 sv = *(const float4*)&s_s[tt][f0];
            float di[4] = {dv.x, dv.y, dv.z, dv.w};
            float xi[4] = {xv.x, xv.y, xv.z, xv.w};
            float cf[4] = {cv.x, cv.y, cv.z, cv.w};
            float sf[4] = {sv.x, sv.y, sv.z, sv.w};
#pragma unroll
            for (int ii = 0; ii < 4; ii++)
#pragma unroll
                for (int ff = 0; ff < 4; ff++) {
                    aDr[ii][ff] += di[ii] * cf[ff];
                    aDi[ii][ff] -= di[ii] * sf[ff];
                    aXr[ii][ff] += xi[ii] * cf[ff];
                    aXi[ii][ff] -= xi[ii] * sf[ff];
                }
        }
        __syncthreads();
    }
    float2* P = (float2*)g_part;
    size_t baseD = (((size_t)0 * BB + b) * nchunk + ch) * 64;
    size_t baseX = (((size_t)1 * BB + b) * nchunk + ch) * 64;
#pragma unroll
    for (int ff = 0; ff < 4; ff++) {
        int f = f0 + ff;
#pragma unroll
        for (int ii = 0; ii < 4; ii++) {
            int i = i0 + ii;
            P[(baseD + f) * 16 + i] = make_float2(aDr[ii][ff], aDi[ii][ff]);
            P[(baseX + f) * 16 + i] = make_float2(aXr[ii][ff], aXi[ii][ff]);
        }
    }
}

// ---------------- reduce partials + complex mode mixing + irfft weighting ----------------
__global__ void mix_kernel(int m, int nchunk) {
    int f = blockIdx.x;
    int b = blockIdx.y;
    int tid = threadIdx.x;          // 32 threads
    __shared__ float Dre[16], Dim[16], Xre[16], Xim[16];
    int arr = tid >> 4, i = tid & 15;
    const float2* P = (const float2*)g_part;
    float sre = 0.f, sim = 0.f;
    for (int ch = 0; ch < nchunk; ch++) {
        float2 p = P[((((size_t)arr * BB + b) * nchunk + ch) * 64 + f) * 16 + i];
        sre += p.x; sim += p.y;
    }
    if (arr == 0) { Dre[i] = sre; Dim[i] = sim; }
    else          { Xre[i] = sre; Xim[i] = sim; }
    __syncthreads();
    float r = 0.f, q = 0.f;
    if (arr == 0) {  // Ud spectrum = D*wA + X*wB
#pragma unroll
        for (int ii = 0; ii < 16; ii++) {
            float ar = g_wT[0 * 16384 + f * 256 + ii * 16 + i];
            float ai = g_wT[1 * 16384 + f * 256 + ii * 16 + i];
            r += Dre[ii] * ar - Dim[ii] * ai;
            q += Dre[ii] * ai + Dim[ii] * ar;
            float br = g_wT[2 * 16384 + f * 256 + ii * 16 + i];
            float bi = g_wT[3 * 16384 + f * 256 + ii * 16 + i];
            r += Xre[ii] * br - Xim[ii] * bi;
            q += Xre[ii] * bi + Xim[ii] * br;
        }
    } else {         // Us spectrum = D*wC
#pragma unroll
        for (int ii = 0; ii < 16; ii++) {
            float cr = g_wT[4 * 16384 + f * 256 + ii * 16 + i];
            float ci = g_wT[5 * 16384 + f * 256 + ii * 16 + i];
            r += Dre[ii] * cr - Dim[ii] * ci;
            q += Dre[ii] * ci + Dim[ii] * cr;
        }
    }
    float wf = (f == 0 || 2 * f == m) ? (1.0f / (float)m) : (2.0f / (float)m);
    g_spec[(((size_t)arr * BB + b) * 64 + f) * 32 + i]      = r * wf;
    g_spec[(((size_t)arr * BB + b) * 64 + f) * 32 + 16 + i] = q * wf;
}

// ---------------- inverse truncated DFT (writes Ud / Us) ----------------
__global__ void __launch_bounds__(128) inv_kernel(float* __restrict__ outUd,
                                                  float* __restrict__ outUs,
                                                  int m, int stride, int l) {
    int b = blockIdx.x;
    int arr = blockIdx.z;
    int tid = threadIdx.x;
    int t1 = blockIdx.y * 256 + tid;
    int t2 = t1 + 128;
    __shared__ __align__(16) float sp[2048];
    for (int idx = tid; idx < l * 32; idx += 128)
        sp[idx] = g_spec[((size_t)arr * BB + b) * 2048 + idx];
    __syncthreads();
    float a1[16], a2[16];
#pragma unroll
    for (int j = 0; j < 16; j++) { a1[j] = 0.f; a2[j] = 0.f; }
    bool v1 = t1 < m, v2 = t2 < m;
    const float2* T = (const float2*)g_tabT;
    size_t tb1 = (size_t)t1 * stride, tb2 = (size_t)t2 * stride;
    for (int f = 0; f < l; f++) {
        float2 cs1 = v1 ? T[(size_t)f * 8192 + tb1] : make_float2(0.f, 0.f);
        float2 cs2 = v2 ? T[(size_t)f * 8192 + tb2] : make_float2(0.f, 0.f);
        float4 r0 = *(const float4*)&sp[f * 32 + 0];
        float4 r1 = *(const float4*)&sp[f * 32 + 4];
        float4 r2 = *(const float4*)&sp[f * 32 + 8];
        float4 r3 = *(const float4*)&sp[f * 32 + 12];
        float4 q0 = *(const float4*)&sp[f * 32 + 16];
        float4 q1 = *(const float4*)&sp[f * 32 + 20];
        float4 q2 = *(const float4*)&sp[f * 32 + 24];
        float4 q3 = *(const float4*)&sp[f * 32 + 28];
        float re[16] = {r0.x, r0.y, r0.z, r0.w, r1.x, r1.y, r1.z, r1.w,
                        r2.x, r2.y, r2.z, r2.w, r3.x, r3.y, r3.z, r3.w};
        float im[16] = {q0.x, q0.y, q0.z, q0.w, q1.x, q1.y, q1.z, q1.w,
                        q2.x, q2.y, q2.z, q2.w, q3.x, q3.y, q3.z, q3.w};
#pragma unroll
        for (int j = 0; j < 16; j++) {
            a1[j] += re[j] * cs1.x - im[j] * cs1.y;
            a2[j] += re[j] * cs2.x - im[j] * cs2.y;
        }
    }
    float* out = ((arr == 0) ? outUd : outUs) + (size_t)b * m * 16;
    if (v1) {
        *(float4*)&out[(size_t)t1 * 16 + 0]  = make_float4(a1[0], a1[1], a1[2], a1[3]);
        *(float4*)&out[(size_t)t1 * 16 + 4]  = make_float4(a1[4], a1[5], a1[6], a1[7]);
        *(float4*)&out[(size_t)t1 * 16 + 8]  = make_float4(a1[8], a1[9], a1[10], a1[11]);
        *(float4*)&out[(size_t)t1 * 16 + 12] = make_float4(a1[12], a1[13], a1[14], a1[15]);
    }
    if (v2) {
        *(float4*)&out[(size_t)t2 * 16 + 0]  = make_float4(a2[0], a2[1], a2[2], a2[3]);
        *(float4*)&out[(size_t)t2 * 16 + 4]  = make_float4(a2[4], a2[5], a2[6], a2[7]);
        *(float4*)&out[(size_t)t2 * 16 + 8]  = make_float4(a2[8], a2[9], a2[10], a2[11]);
        *(float4*)&out[(size_t)t2 * 16 + 12] = make_float4(a2[12], a2[13], a2[14], a2[15]);
    }
}

// ---------------- coarsest-scale T0 ----------------
__global__ void t0_kernel(const float* __restrict__ xin, const float* __restrict__ t0w,
                          const float* __restrict__ t0b, float* __restrict__ xout) {
    int idx = threadIdx.x;   // 128 = 32b * 4c
    if (idx >= 128) return;
    int b = idx >> 2, c = idx & 3;
    float4 xv = *(const float4*)&xin[b * 16 + c * 4];
    float x[4] = {xv.x, xv.y, xv.z, xv.w};
    float y[4];
#pragma unroll
    for (int j = 0; j < 4; j++) {
        float acc = t0b[j];
#pragma unroll
        for (int p = 0; p < 4; p++) acc += x[p] * t0w[j * 4 + p];
        y[j] = acc;
    }
    *(float4*)&xout[b * 16 + c * 4] = make_float4(y[0], y[1], y[2], y[3]);
}

// ---------------- reconstruction step (x += Us; even/odd filter; interleave) ----------------
__global__ void recon_kernel(const float* __restrict__ xin, const float* __restrict__ Ud,
                             const float* __restrict__ Us, const float* __restrict__ rce,
                             const float* __restrict__ rco, float* __restrict__ out, int m) {
    __shared__ float se[32], so[32];
    int tid = threadIdx.x;
    if (tid < 32)      se[tid]      = rce[tid];
    else if (tid < 64) so[tid - 32] = rco[tid - 32];
    __syncthreads();
    int idx = blockIdx.x * blockDim.x + tid;
    if (idx >= BB * m * 4) return;
    int c = idx & 3;
    int s = (idx >> 2) % m;
    int b = idx / (m * 4);
    size_t r = ((size_t)b * m + s) * 16 + c * 4;
    float4 xv = *(const float4*)&xin[r];
    float4 uv = *(const float4*)&Us[r];
    float4 dv = *(const float4*)&Ud[r];
    float xs[4] = {xv.x + uv.x, xv.y + uv.y, xv.z + uv.z, xv.w + uv.w};
    float ud[4] = {dv.x, dv.y, dv.z, dv.w};
    float e[4] = {0, 0, 0, 0}, o[4] = {0, 0, 0, 0};
#pragma unroll
    for (int p = 0; p < 4; p++)
#pragma unroll
        for (int j = 0; j < 4; j++) {
            e[j] += xs[p] * se[p * 4 + j] + ud[p] * se[(p + 4) * 4 + j];
            o[j] += xs[p] * so[p * 4 + j] + ud[p] * so[(p + 4) * 4 + j];
        }
    size_t w = ((size_t)b * 2 * m + 2 * s) * 16 + c * 4;
    *(float4*)&out[w]      = make_float4(e[0], e[1], e[2], e[3]);
    *(float4*)&out[w + 16] = make_float4(o[0], o[1], o[2], o[3]);
}

// ---------------- host orchestration ----------------
extern "C" void kernel_launch(void* const* d_in, const int* in_sizes, int n_in,
                              void* d_out, int out_size) {
    const float* x_in = (const float*)d_in[0];
    const float* ec_s = (const float*)d_in[1];
    const float* ec_d = (const float*)d_in[2];
    const float* rc_e = (const float*)d_in[3];
    const float* rc_o = (const float*)d_in[4];
    const float* t0_w = (const float*)d_in[5];
    const float* t0_b = (const float*)d_in[6];

    tab_row_kernel<<<2048, 256>>>();
    tab_T_kernel<<<2048, 256>>>();
    wprep_kernel<<<(6 * 16384 + 255) / 256, 256>>>(
        (const float*)d_in[7], (const float*)d_in[8], (const float*)d_in[9],
        (const float*)d_in[10], (const float*)d_in[11], (const float*)d_in[12]);

    float *px0, *px1, *pd, *pUd, *pUs;
    cudaGetSymbolAddress((void**)&px0, g_x0);
    cudaGetSymbolAddress((void**)&px1, g_x1);
    cudaGetSymbolAddress((void**)&pd,  g_d);
    cudaGetSymbolAddress((void**)&pUd, g_Ud);
    cudaGetSymbolAddress((void**)&pUs, g_Us);

    float* xb[2] = {px0, px1};
    const float* src = x_in;
    int cur = -1;
    size_t off = 0;
    size_t offs[NS];

    for (int lev = 0; lev < NS; lev++) {
        int m = NN >> (lev + 1);
        offs[lev] = off;
        int nxt = (cur + 1) & 1;
        int total = BB * m * 4;
        decompose_kernel<<<(total + 255) / 256, 256>>>(src, ec_d, ec_s, pd, xb[nxt], m);

        int l = (m / 2 + 1 < 64) ? (m / 2 + 1) : 64;
        int stride = MAXM / m;
        int nchunk = m / 128; if (nchunk < 1) nchunk = 1;

        fwd_kernel<<<dim3(BB, nchunk), 64>>>(pd, xb[nxt], m, stride, nchunk);
        mix_kernel<<<dim3(l, BB), 32>>>(m, nchunk);
        inv_kernel<<<dim3(BB, (m + 255) / 256, 2), 128>>>(
            pUd + (size_t)BB * CKD * off, pUs + (size_t)BB * CKD * off, m, stride, l);

        off += m;
        src = xb[nxt];
        cur = nxt;
    }

    // coarsest linear map
    int nxt = cur ^ 1;
    t0_kernel<<<1, 128>>>(src, t0_w, t0_b, xb[nxt]);
    const float* curx = xb[nxt];
    cur = nxt;

    for (int lev = NS - 1; lev >= 0; lev--) {
        int m = NN >> (lev + 1);
        float* dst = (lev == 0) ? (float*)d_out : xb[cur ^ 1];
        int total = BB * m * 4;
        recon_kernel<<<(total + 255) / 256, 256>>>(
            curx, pUd + (size_t)BB * CKD * offs[lev], pUs + (size_t)BB * CKD * offs[lev],
            rc_e, rc_o, dst, m);
        curx = dst;
        cur ^= 1;
    }
}